// round 14
// baseline (speedup 1.0000x reference)
#include <cuda_runtime.h>
#include <cuda_fp16.h>
#include <math.h>
#include <stdint.h>

#define B_  32
#define S_  512
#define D_  9
#define E_  256
#define F_  1024
#define L_  4
#define C_  10
#define H_  8
#define HD_ 32
#define M_  (B_*S_)          // 16384 rows
#define KV_LD 512

// ---------------- scratch (static __device__, no allocs) ----------------
__device__ float g_ah[B_*H_*S_];      // per-head attn last rows (scaled 1/8)
__device__ float g_part[B_*16*E_];    // decode partial sums
__device__ int   g_tick[B_];          // combine tickets (self-resetting)

__device__ __half gx_h[M_*E_];        // activations fp16 (residual master)
__device__ __half gk_h[M_*KV_LD];     // k(0..255), v->o(256..511) fp16
__device__ __half gh_h[M_*F_];        // ffn hidden fp16
__device__ __half gy_h[M_*E_];        // proj/ffn2 out fp16
__device__ __half wq_h[L_*3*E_*E_];
__device__ __half wo_h[L_*E_*E_];
__device__ __half w1_h[L_*F_*E_];
__device__ __half w2_h[L_*E_*F_];

// ================= PTX helpers (target-portable) =================
__device__ __forceinline__ uint32_t smem_u32(const void* p) {
    uint32_t a;
    asm("{ .reg .u64 t; cvta.to.shared.u64 t, %1; cvt.u32.u64 %0, t; }" : "=r"(a) : "l"(p));
    return a;
}
__device__ __forceinline__ void cp16(uint32_t dst, const void* src) {
    asm volatile("cp.async.cg.shared.global [%0], [%1], 16;\n" :: "r"(dst), "l"(src));
}
__device__ __forceinline__ void ldsm4(uint32_t* r, uint32_t addr) {
    asm volatile("ldmatrix.sync.aligned.m8n8.x4.shared.b16 {%0,%1,%2,%3}, [%4];"
        : "=r"(r[0]), "=r"(r[1]), "=r"(r[2]), "=r"(r[3]) : "r"(addr));
}
__device__ __forceinline__ void mma16816(float* d, const uint32_t* a, const uint32_t* b) {
    asm volatile("mma.sync.aligned.m16n8k16.row.col.f32.f16.f16.f32 "
        "{%0,%1,%2,%3}, {%4,%5,%6,%7}, {%8,%9}, {%0,%1,%2,%3};"
        : "+f"(d[0]), "+f"(d[1]), "+f"(d[2]), "+f"(d[3])
        : "r"(a[0]), "r"(a[1]), "r"(a[2]), "r"(a[3]), "r"(b[0]), "r"(b[1]));
}

// ================= GEMM: C[M,N] = A[M,K] @ B[N,K]^T + bias =================
// BM=BN=128, BK=64, 256 threads, warp grid 2x4, warp tile 64x32,
// 3-stage cp.async pipeline @ 32KB/stage -> 97KB/CTA -> still 2 CTAs/SM.
#define STAGES 3
#define STAGE_BYTES 32768          // A 16K | B 16K
#define SMEM_REQ (STAGES*STAGE_BYTES + 1024)

__global__ __launch_bounds__(256, 2)
void gemm_mma(const __half* __restrict__ Ah, int lda,
              const __half* __restrict__ Bh,
              const float* __restrict__ bias,
              __half* __restrict__ outH,
              int N, int K, int mode)
{
    extern __shared__ char dsm[];
    const uint32_t base = (smem_u32(dsm) + 1023u) & ~1023u;
    const int tid = threadIdx.x;
    const int lane = tid & 31, wid = tid >> 5;
    const int bm = blockIdx.y * 128, bn = blockIdx.x * 128;
    const int wm = wid >> 2, wn = wid & 3;

    const size_t lda2 = (size_t)lda * 2, ldb2 = (size_t)K * 2;
    const char* gAh = (const char*)Ah + (size_t)bm * lda2;
    const char* gBh = (const char*)Bh + (size_t)bn * ldb2;

    const int cc  = tid & 7;
    const int rr0 = tid >> 3;

    auto load_stage = [&](int kt, int s) {
        uint32_t st = base + (uint32_t)s * STAGE_BYTES;
        size_t gk = (size_t)kt * 128 + (size_t)cc * 16;
        #pragma unroll
        for (int j = 0; j < 4; j++) {
            int r = rr0 + j * 32;
            uint32_t d = (uint32_t)(r * 128 + ((cc ^ (r & 7)) << 4));
            cp16(st + d,           gAh + (size_t)r * lda2 + gk);
            cp16(st + 16384 + d,   gBh + (size_t)r * ldb2 + gk);
        }
        asm volatile("cp.async.commit_group;\n" ::: "memory");
    };

    const int q = lane >> 3, r8 = lane & 7;
    int mRow[4], mSel[4];
    #pragma unroll
    for (int mt = 0; mt < 4; mt++) {
        int m = wm * 64 + mt * 16 + r8 + (q & 1) * 8;
        mRow[mt] = m * 128; mSel[mt] = m & 7;
    }
    const int aKH = q >> 1;
    int nRow[2], nSel[2];
    #pragma unroll
    for (int ng = 0; ng < 2; ng++) {
        int n = wn * 32 + ng * 16 + r8 + (q >> 1) * 8;
        nRow[ng] = n * 128; nSel[ng] = n & 7;
    }
    const int bKH = q & 1;

    float acc[4][4][4];
    #pragma unroll
    for (int a = 0; a < 4; a++)
        #pragma unroll
        for (int b = 0; b < 4; b++)
            #pragma unroll
            for (int c = 0; c < 4; c++) acc[a][b][c] = 0.f;

    const int nkt = K >> 6;
    load_stage(0, 0);
    if (nkt > 1) load_stage(1, 1);

    for (int kt = 0; kt < nkt; kt++) {
        if (kt + 2 < nkt) load_stage(kt + 2, (kt + 2) % STAGES);
        else asm volatile("cp.async.commit_group;\n" ::: "memory");
        asm volatile("cp.async.wait_group 2;\n" ::: "memory");
        __syncthreads();

        const uint32_t sb = base + (uint32_t)(kt % STAGES) * STAGE_BYTES;
        #pragma unroll
        for (int ks = 0; ks < 4; ks++) {
            uint32_t ah[4][4], bh[2][4];
            #pragma unroll
            for (int mt = 0; mt < 4; mt++) {
                uint32_t off = (uint32_t)(mRow[mt] + (((ks * 2 + aKH) ^ mSel[mt]) << 4));
                ldsm4(ah[mt], sb + off);
            }
            #pragma unroll
            for (int ng = 0; ng < 2; ng++) {
                uint32_t off = (uint32_t)(nRow[ng] + (((ks * 2 + bKH) ^ nSel[ng]) << 4));
                ldsm4(bh[ng], sb + 16384 + off);
            }
            #pragma unroll
            for (int mt = 0; mt < 4; mt++)
                #pragma unroll
                for (int nt = 0; nt < 4; nt++)
                    mma16816(acc[mt][nt], ah[mt], &bh[nt >> 1][(nt & 1) * 2]);
        }
        __syncthreads();
    }

    const int mE = lane >> 2;
    const int nE = (lane & 3) << 1;
    #pragma unroll
    for (int mt = 0; mt < 4; mt++) {
        #pragma unroll
        for (int nt = 0; nt < 4; nt++) {
            int m0 = bm + wm * 64 + mt * 16 + mE;
            int n0 = bn + wn * 32 + nt * 8 + nE;
            float b0v = bias[n0], b1v = bias[n0 + 1];
            float v00 = acc[mt][nt][0] + b0v;
            float v01 = acc[mt][nt][1] + b1v;
            float v10 = acc[mt][nt][2] + b0v;
            float v11 = acc[mt][nt][3] + b1v;
            if (mode == 1) {
                v00 = fmaxf(v00, 0.f); v01 = fmaxf(v01, 0.f);
                v10 = fmaxf(v10, 0.f); v11 = fmaxf(v11, 0.f);
            }
            size_t i0 = (size_t)m0 * N + n0;
            size_t i1 = (size_t)(m0 + 8) * N + n0;
            *(__half2*)(outH + i0) = __halves2half2(__float2half(v00), __float2half(v01));
            *(__half2*)(outH + i1) = __halves2half2(__float2half(v10), __float2half(v11));
        }
    }
}

// ---------------- all weights -> fp16 (one launch) ----------------
__global__ void splitAll_kernel(const float* __restrict__ Wqkv,
                                const float* __restrict__ Wo,
                                const float* __restrict__ W1,
                                const float* __restrict__ W2) {
    const int n0 = L_*3*E_*E_;
    const int n1 = n0 + L_*E_*E_;
    const int n2 = n1 + L_*F_*E_;
    const int n3 = n2 + L_*E_*F_;
    int i = blockIdx.x * blockDim.x + threadIdx.x;
    int stride = gridDim.x * blockDim.x;
    for (; i < n3; i += stride) {
        if (i < n0)      wq_h[i]      = __float2half(Wqkv[i]);
        else if (i < n1) wo_h[i - n0] = __float2half(Wo[i - n0]);
        else if (i < n2) w1_h[i - n1] = __float2half(W1[i - n1]);
        else             w2_h[i - n2] = __float2half(W2[i - n2]);
    }
}

// ---------------- warp reductions ----------------
__device__ __forceinline__ float warpSum(float v) {
    #pragma unroll
    for (int o = 16; o > 0; o >>= 1) v += __shfl_xor_sync(0xffffffffu, v, o);
    return v;
}
__device__ __forceinline__ float warpMax(float v) {
    #pragma unroll
    for (int o = 16; o > 0; o >>= 1) v = fmaxf(v, __shfl_xor_sync(0xffffffffu, v, o));
    return v;
}
__device__ float blockSum(float v, float* red) {
    int lane = threadIdx.x & 31, wid = threadIdx.x >> 5;
    v = warpSum(v);
    if (lane == 0) red[wid] = v;
    __syncthreads();
    if (wid == 0) {
        float x = (lane < 8) ? red[lane] : 0.f;
        x = warpSum(x);
        if (lane == 0) red[0] = x;
    }
    __syncthreads();
    float r = red[0];
    __syncthreads();
    return r;
}
__device__ float blockMax(float v, float* red) {
    int lane = threadIdx.x & 31, wid = threadIdx.x >> 5;
    v = warpMax(v);
    if (lane == 0) red[wid] = v;
    __syncthreads();
    if (wid == 0) {
        float x = (lane < 8) ? red[lane] : -1e30f;
        x = warpMax(x);
        if (lane == 0) red[0] = x;
    }
    __syncthreads();
    float r = red[0];
    __syncthreads();
    return r;
}

// ---------------- embed + posenc: 8 rows/block, 1 sincos + rotation ----------------
__global__ __launch_bounds__(256)
void embed_kernel(const float* __restrict__ src,
                  const float* __restrict__ embW,
                  const float* __restrict__ embb) {
    int e = threadIdx.x;
    int m0 = blockIdx.x * 8;
    float w[D_];
    #pragma unroll
    for (int d = 0; d < D_; d++) w[d] = embW[e*D_ + d];
    float be = embb[e];
    const float c = -9.210340371976184f / (float)E_;
    float freq = expf((float)((e >> 1) * 2) * c);
    bool isCos = (e & 1);
    int s0 = m0 & (S_-1);
    float sa, ca, sf, cf;
    sincosf((float)s0 * freq, &sa, &ca);
    sincosf(freq, &sf, &cf);
    #pragma unroll
    for (int r = 0; r < 8; r++) {
        int m = m0 + r;
        const float* sr = src + (size_t)m * D_;
        float acc = 0.f;
        #pragma unroll
        for (int d = 0; d < D_; d++) acc += sr[d] * w[d];
        float pe  = isCos ? ca : sa;
        float val = (acc + be) * 16.0f + pe;
        gx_h[(size_t)m*E_ + e] = __float2half(val);
        float sn = sa*cf + ca*sf;
        ca = ca*cf - sa*sf;
        sa = sn;
    }
}

// ---------------- sparse attention: one block per (head, batch) ----------------
__global__ __launch_bounds__(256)
void attn_kernel(float* __restrict__ out_attn, int l,
                 const float* __restrict__ Wq, const float* __restrict__ bq) {
    int h = blockIdx.x;
    int b = blockIdx.y;
    int t = threadIdx.x;
    __shared__ float xlast[E_];
    __shared__ float qpart[8*HD_];
    __shared__ float q_sh[HD_];
    __shared__ float sc[S_];
    __shared__ float red[32];
    __shared__ float opart[8*HD_];
    __shared__ int lastFlag;
    const float scale = 0.17677669529663687f;
    const __half* kv = gk_h;
    size_t rowLast = (size_t)(b*S_ + (S_-1)) * KV_LD;

    xlast[t] = __half2float(gx_h[(size_t)(b*S_ + (S_-1))*E_ + t]);
    __syncthreads();
    {
        int o = t & 31, cIdx = t >> 5;
        const float* wr = Wq + (size_t)(h*HD_ + o) * E_ + cIdx * 32;
        const float* xr = xlast + cIdx * 32;
        float a = 0.f;
        #pragma unroll
        for (int j = 0; j < 32; j++) a += xr[j] * wr[j];
        qpart[cIdx*HD_ + o] = a;
    }
    __syncthreads();
    if (t < HD_) {
        float a = 0.f;
        #pragma unroll
        for (int cIdx = 0; cIdx < 8; cIdx++) a += qpart[cIdx*HD_ + t];
        q_sh[t] = a + bq[h*HD_ + t];
    }
    __syncthreads();

    float s1, s2;
    {
        const __half* kr = kv + (size_t)(b*S_ + t)*KV_LD + h*HD_;
        float a = 0.f;
        #pragma unroll
        for (int d = 0; d < HD_; d++) a += q_sh[d]*__half2float(kr[d]);
        s1 = a * scale;
        int k2 = t + 256;
        if (k2 != S_-1) {
            const __half* kr2 = kv + (size_t)(b*S_ + k2)*KV_LD + h*HD_;
            float a2 = 0.f;
            #pragma unroll
            for (int d = 0; d < HD_; d++) a2 += q_sh[d]*__half2float(kr2[d]);
            s2 = a2 * scale;
        } else s2 = -1e30f;
    }
    float mx  = blockMax(fmaxf(s1, s2), red);
    float e1  = expf(s1 - mx);
    float e2  = (t + 256 == S_-1) ? 0.f : expf(s2 - mx);
    float sum = blockSum(e1 + e2, red);
    float inv = 1.0f / sum;
    float a1 = e1*inv, a2 = e2*inv;
    sc[t] = a1; sc[t+256] = a2;
    float* ah = g_ah + ((size_t)b*H_ + h) * S_;
    ah[t]       = a1 * 0.125f;
    ah[t+256]   = a2 * 0.125f;
    __syncthreads();

    int g = t >> 5, d = t & 31;
    float oa = 0.f;
    for (int k = g; k < S_-1; k += 8)
        oa += sc[k] * __half2float(kv[(size_t)(b*S_ + k)*KV_LD + E_ + h*HD_ + d]);
    opart[g*HD_ + d] = oa;
    __syncthreads();
    if (t < HD_) {
        float o = 0.f;
        #pragma unroll
        for (int gg = 0; gg < 8; gg++) o += opart[gg*HD_ + t];
        gk_h[rowLast + E_ + h*HD_ + t] = __float2half(o);
    }

    __syncthreads();
    __threadfence();
    if (t == 0) lastFlag = (atomicAdd(&g_tick[b], 1) == H_-1) ? 1 : 0;
    __syncthreads();
    if (lastFlag) {
        if (t == 0) g_tick[b] = 0;
        float s0 = 0.f, ss1 = 0.f;
        #pragma unroll
        for (int hh = 0; hh < H_; hh++) {
            const float* ar = g_ah + ((size_t)b*H_ + hh) * S_;
            s0  += ar[t];
            ss1 += ar[t + 256];
        }
        size_t basei = ((size_t)(l*B_ + b)*S_ + (S_-1)) * S_;
        out_attn[basei + t]       = s0;
        out_attn[basei + t + 256] = ss1;
    }
}

// ---------------- residual + layernorm: warp-per-row, fp16 in/out ----------------
__global__ __launch_bounds__(256)
void ln_kernel(const __half* __restrict__ y, int ldy,
               const float* __restrict__ g, const float* __restrict__ bb) {
    int w = threadIdx.x >> 5, lane = threadIdx.x & 31;
    int m = blockIdx.x * 8 + w;
    size_t xb = (size_t)m * E_ + lane * 4;
    const __half2* x0 = (const __half2*)(gx_h + xb);
    const __half2* x1 = (const __half2*)(gx_h + xb + 128);
    float2 a0 = __half22float2(x0[0]), a1 = __half22float2(x0[1]);
    float2 a2 = __half22float2(x1[0]), a3 = __half22float2(x1[1]);
    const __half2* y0 = (const __half2*)(y + (size_t)m*ldy + lane*4);
    const __half2* y1 = (const __half2*)(y + (size_t)m*ldy + 128 + lane*4);
    float2 f0 = __half22float2(y0[0]), f1 = __half22float2(y0[1]);
    float2 f2 = __half22float2(y1[0]), f3 = __half22float2(y1[1]);
    float v0 = a0.x + f0.x, v1 = a0.y + f0.y, v2 = a1.x + f1.x, v3 = a1.y + f1.y;
    float v4 = a2.x + f2.x, v5 = a2.y + f2.y, v6 = a3.x + f3.x, v7 = a3.y + f3.y;
    float s = v0+v1+v2+v3+v4+v5+v6+v7;
    float mean = warpSum(s) * (1.0f/E_);
    float d0=v0-mean, d1=v1-mean, d2=v2-mean, d3=v3-mean;
    float d4=v4-mean, d5=v5-mean, d6=v6-mean, d7=v7-mean;
    float qs = d0*d0+d1*d1+d2*d2+d3*d3+d4*d4+d5*d5+d6*d6+d7*d7;
    float var = warpSum(qs) * (1.0f/E_);
    float inv = rsqrtf(var + 1e-5f);
    int e0 = lane * 4;
    float4 ga = *(const float4*)(g + e0);
    float4 gc = *(const float4*)(g + e0 + 128);
    float4 ba = *(const float4*)(bb + e0);
    float4 bc = *(const float4*)(bb + e0 + 128);
    float r0 = d0*inv*ga.x + ba.x, r1 = d1*inv*ga.y + ba.y;
    float r2 = d2*inv*ga.z + ba.z, r3 = d3*inv*ga.w + ba.w;
    float r4 = d4*inv*gc.x + bc.x, r5 = d5*inv*gc.y + bc.y;
    float r6 = d6*inv*gc.z + bc.z, r7 = d7*inv*gc.w + bc.w;
    __half2* oh0 = (__half2*)(gx_h + xb);
    __half2* oh1 = (__half2*)(gx_h + xb + 128);
    oh0[0] = __halves2half2(__float2half(r0), __float2half(r1));
    oh0[1] = __halves2half2(__float2half(r2), __float2half(r3));
    oh1[0] = __halves2half2(__float2half(r4), __float2half(r5));
    oh1[1] = __halves2half2(__float2half(r6), __float2half(r7));
}

// ---------------- decode head (2-phase) ----------------
__global__ __launch_bounds__(256)
void final_part1(void) {
    int b = blockIdx.x, c = blockIdx.y, e = threadIdx.x;
    float acc = 0.f;
    int s0 = c * 32;
    #pragma unroll 8
    for (int s = s0; s < s0 + 32; s++)
        acc += fmaxf(__half2float(gx_h[((size_t)b*S_ + s)*E_ + e]), 0.f);
    g_part[((size_t)b*16 + c)*E_ + e] = acc;
}

__global__ __launch_bounds__(256)
void final_part2(const float* __restrict__ decW, float* __restrict__ out) {
    int b = blockIdx.x, e = threadIdx.x;
    __shared__ float xs[E_];
    __shared__ float lg[C_];
    __shared__ float lse_s;
    float acc = 0.f;
    #pragma unroll
    for (int c = 0; c < 16; c++)
        acc += g_part[((size_t)b*16 + c)*E_ + e];
    xs[e] = acc * (1.0f/S_);
    __syncthreads();
    if (e < C_) {
        float a = 0.f;
        for (int i = 0; i < E_; i++) a += xs[i]*decW[e*E_ + i];
        lg[e] = a;
    }
    __syncthreads();
    if (e == 0) {
        float m = -1e30f;
        for (int c = 0; c < C_; c++) m = fmaxf(m, lg[c]);
        float s = 0.f;
        for (int c = 0; c < C_; c++) s += expf(lg[c]-m);
        lse_s = m + logf(s);
    }
    __syncthreads();
    if (e < C_) out[b*C_ + e] = lg[e] - lse_s;
}

// ---------------- attns constant fill (single pass) ----------------
__global__ void fill_attns(float4* __restrict__ p, int n4) {
    int i = blockIdx.x*blockDim.x + threadIdx.x;
    int stride = gridDim.x*blockDim.x;
    for (; i < n4; i += stride) {
        int e0 = i * 4;
        int k0 = e0 & (S_-1);
        int q  = (e0 >> 9) & (S_-1);
        float4 v = make_float4(0.f,0.f,0.f,0.f);
        if (q != S_-1) {
            if (k0 == (q & ~3)) {
                int off = q & 3;
                ((float*)&v)[off] = 1.0f;
            }
        }
        p[i] = v;
    }
}

// ---------------- host ----------------
extern "C" void kernel_launch(void* const* d_in, const int* in_sizes, int n_in,
                              void* d_out, int out_size) {
    const float* src   = (const float*)d_in[0];
    const float* embW  = (const float*)d_in[1];
    const float* embb  = (const float*)d_in[2];
    const float* Wqkv  = (const float*)d_in[3];
    const float* bqkv  = (const float*)d_in[4];
    const float* Wo    = (const float*)d_in[5];
    const float* bo    = (const float*)d_in[6];
    const float* ln1g  = (const float*)d_in[7];
    const float* ln1b  = (const float*)d_in[8];
    const float* ln2g  = (const float*)d_in[9];
    const float* ln2b  = (const float*)d_in[10];
    const float* W1    = (const float*)d_in[11];
    const float* b1    = (const float*)d_in[12];
    const float* W2    = (const float*)d_in[13];
    const float* b2    = (const float*)d_in[14];
    const float* decW  = (const float*)d_in[15];
    float* out = (float*)d_out;
    float* out_attn = out + B_*C_;

    __half *xh, *kh, *hh, *yh;
    __half *wqh, *woh, *w1h, *w2h;
    cudaGetSymbolAddress((void**)&xh, gx_h);
    cudaGetSymbolAddress((void**)&kh, gk_h);
    cudaGetSymbolAddress((void**)&hh, gh_h);
    cudaGetSymbolAddress((void**)&yh, gy_h);
    cudaGetSymbolAddress((void**)&wqh, wq_h);
    cudaGetSymbolAddress((void**)&woh, wo_h);
    cudaGetSymbolAddress((void**)&w1h, w1_h);
    cudaGetSymbolAddress((void**)&w2h, w2_h);

    cudaFuncSetAttribute(gemm_mma, cudaFuncAttributeMaxDynamicSharedMemorySize, SMEM_REQ);

    static cudaStream_t s2 = 0;
    static cudaEvent_t evFork = 0, evSplit = 0, evFill = 0;
    if (!s2) {
        cudaStreamCreateWithFlags(&s2, cudaStreamNonBlocking);
        cudaEventCreateWithFlags(&evFork,  cudaEventDisableTiming);
        cudaEventCreateWithFlags(&evSplit, cudaEventDisableTiming);
        cudaEventCreateWithFlags(&evFill,  cudaEventDisableTiming);
    }

    // fork side stream (one-time): weight split + attns fill
    cudaEventRecord(evFork, 0);
    cudaStreamWaitEvent(s2, evFork, 0);
    splitAll_kernel<<<1536, 256, 0, s2>>>(Wqkv, Wo, W1, W2);
    cudaEventRecord(evSplit, s2);
    int n4 = (L_*B_*S_*S_) / 4;
    fill_attns<<<4096, 256, 0, s2>>>((float4*)out_attn, n4);
    cudaEventRecord(evFill, s2);

    // main stream: embed overlaps side stream
    embed_kernel<<<M_/8, 256>>>(src, embW, embb);
    cudaStreamWaitEvent(0, evSplit, 0);

    for (int l = 0; l < L_; l++) {
        const size_t wq_off = (size_t)l*3*E_*E_;
        // kv = x @ [Wk;Wv]^T + b   [16384,512] -> fp16
        gemm_mma<<<dim3(4, 128), 256, SMEM_REQ>>>(
            xh, E_, wqh + wq_off + (size_t)E_*E_,
            bqkv + l*3*E_ + E_, kh, KV_LD, E_, 0);
        if (l == 0) cudaStreamWaitEvent(0, evFill, 0);
        // attention per (head, batch) + fused ticket combine
        attn_kernel<<<dim3(H_, B_), 256>>>(out_attn, l, Wqkv + wq_off, bqkv + l*3*E_);
        // y = o @ Wo^T + bo  (o = v-view of kh, lda=512) -> fp16
        gemm_mma<<<dim3(2, 128), 256, SMEM_REQ>>>(
            kh + E_, KV_LD, woh + (size_t)l*E_*E_,
            bo + l*E_, yh, E_, E_, 0);
        // x = LN1(x + y)
        ln_kernel<<<M_/8, 256>>>(yh, E_, ln1g + l*E_, ln1b + l*E_);
        // h = relu(x @ W1^T + b1) -> fp16
        gemm_mma<<<dim3(8, 128), 256, SMEM_REQ>>>(
            xh, E_, w1h + (size_t)l*F_*E_,
            b1 + l*F_, hh, F_, E_, 1);
        // y = h @ W2^T + b2 -> fp16
        gemm_mma<<<dim3(2, 128), 256, SMEM_REQ>>>(
            hh, F_, w2h + (size_t)l*E_*F_,
            b2 + l*E_, yh, E_, F_, 0);
        // x = LN2(x + y)
        ln_kernel<<<M_/8, 256>>>(yh, E_, ln2g + l*E_, ln2b + l*E_);
    }

    final_part1<<<dim3(B_, 16), 256>>>();
    final_part2<<<B_, 256>>>(decW, out);
}

// round 15
// speedup vs baseline: 1.0902x; 1.0902x over previous
#include <cuda_runtime.h>
#include <cuda_fp16.h>
#include <math.h>
#include <stdint.h>

#define B_  32
#define S_  512
#define D_  9
#define E_  256
#define F_  1024
#define L_  4
#define C_  10
#define H_  8
#define HD_ 32
#define M_  (B_*S_)          // 16384 rows
#define KV_LD 512

// ---------------- scratch (static __device__, no allocs) ----------------
__device__ float g_ah[B_*H_*S_];      // per-head attn last rows (scaled 1/8)
__device__ float g_part[B_*16*E_];    // decode partial sums
__device__ int   g_tick[B_];          // combine tickets (self-resetting)

__device__ __half gx_h[M_*E_];        // activations fp16 (residual master)
__device__ __half gk_h[M_*KV_LD];     // k(0..255), v->o(256..511) fp16
__device__ __half gh_h[M_*F_];        // ffn hidden fp16
__device__ __half gy_h[M_*E_];        // proj/ffn2 out fp16
__device__ __half wq_h[L_*3*E_*E_];
__device__ __half wo_h[L_*E_*E_];
__device__ __half w1_h[L_*F_*E_];
__device__ __half w2_h[L_*E_*F_];

// ================= PTX helpers (target-portable) =================
__device__ __forceinline__ uint32_t smem_u32(const void* p) {
    uint32_t a;
    asm("{ .reg .u64 t; cvta.to.shared.u64 t, %1; cvt.u32.u64 %0, t; }" : "=r"(a) : "l"(p));
    return a;
}
__device__ __forceinline__ void cp16(uint32_t dst, const void* src) {
    asm volatile("cp.async.cg.shared.global [%0], [%1], 16;\n" :: "r"(dst), "l"(src));
}
__device__ __forceinline__ void ldsm4(uint32_t* r, uint32_t addr) {
    asm volatile("ldmatrix.sync.aligned.m8n8.x4.shared.b16 {%0,%1,%2,%3}, [%4];"
        : "=r"(r[0]), "=r"(r[1]), "=r"(r[2]), "=r"(r[3]) : "r"(addr));
}
__device__ __forceinline__ void mma16816(float* d, const uint32_t* a, const uint32_t* b) {
    asm volatile("mma.sync.aligned.m16n8k16.row.col.f32.f16.f16.f32 "
        "{%0,%1,%2,%3}, {%4,%5,%6,%7}, {%8,%9}, {%0,%1,%2,%3};"
        : "+f"(d[0]), "+f"(d[1]), "+f"(d[2]), "+f"(d[3])
        : "r"(a[0]), "r"(a[1]), "r"(a[2]), "r"(a[3]), "r"(b[0]), "r"(b[1]));
}

// ================= GEMM: C[M,N] = A[M,K] @ B[N,K]^T + bias =================
// BM=BN=128, BK=64, 256 threads, warp grid 2x4, warp tile 64x32,
// 2-stage cp.async pipeline, 2 CTAs/SM. (PROVEN optimum — frozen.)
#define STAGES 2
#define STAGE_BYTES 32768          // A 16K | B 16K
#define SMEM_REQ (STAGES*STAGE_BYTES + 1024)

__global__ __launch_bounds__(256, 2)
void gemm_mma(const __half* __restrict__ Ah, int lda,
              const __half* __restrict__ Bh,
              const float* __restrict__ bias,
              __half* __restrict__ outH,
              int N, int K, int mode)
{
    extern __shared__ char dsm[];
    const uint32_t base = (smem_u32(dsm) + 1023u) & ~1023u;
    const int tid = threadIdx.x;
    const int lane = tid & 31, wid = tid >> 5;
    const int bm = blockIdx.y * 128, bn = blockIdx.x * 128;
    const int wm = wid >> 2, wn = wid & 3;

    const size_t lda2 = (size_t)lda * 2, ldb2 = (size_t)K * 2;
    const char* gAh = (const char*)Ah + (size_t)bm * lda2;
    const char* gBh = (const char*)Bh + (size_t)bn * ldb2;

    const int cc  = tid & 7;
    const int rr0 = tid >> 3;

    auto load_stage = [&](int kt, int s) {
        uint32_t st = base + (uint32_t)s * STAGE_BYTES;
        size_t gk = (size_t)kt * 128 + (size_t)cc * 16;
        #pragma unroll
        for (int j = 0; j < 4; j++) {
            int r = rr0 + j * 32;
            uint32_t d = (uint32_t)(r * 128 + ((cc ^ (r & 7)) << 4));
            cp16(st + d,           gAh + (size_t)r * lda2 + gk);
            cp16(st + 16384 + d,   gBh + (size_t)r * ldb2 + gk);
        }
        asm volatile("cp.async.commit_group;\n" ::: "memory");
    };

    const int q = lane >> 3, r8 = lane & 7;
    int mRow[4], mSel[4];
    #pragma unroll
    for (int mt = 0; mt < 4; mt++) {
        int m = wm * 64 + mt * 16 + r8 + (q & 1) * 8;
        mRow[mt] = m * 128; mSel[mt] = m & 7;
    }
    const int aKH = q >> 1;
    int nRow[2], nSel[2];
    #pragma unroll
    for (int ng = 0; ng < 2; ng++) {
        int n = wn * 32 + ng * 16 + r8 + (q >> 1) * 8;
        nRow[ng] = n * 128; nSel[ng] = n & 7;
    }
    const int bKH = q & 1;

    float acc[4][4][4];
    #pragma unroll
    for (int a = 0; a < 4; a++)
        #pragma unroll
        for (int b = 0; b < 4; b++)
            #pragma unroll
            for (int c = 0; c < 4; c++) acc[a][b][c] = 0.f;

    const int nkt = K >> 6;
    load_stage(0, 0);

    for (int kt = 0; kt < nkt; kt++) {
        if (kt + 1 < nkt) load_stage(kt + 1, (kt + 1) & 1);
        else asm volatile("cp.async.commit_group;\n" ::: "memory");
        asm volatile("cp.async.wait_group 1;\n" ::: "memory");
        __syncthreads();

        const uint32_t sb = base + (uint32_t)(kt & 1) * STAGE_BYTES;
        #pragma unroll
        for (int ks = 0; ks < 4; ks++) {
            uint32_t ah[4][4], bh[2][4];
            #pragma unroll
            for (int mt = 0; mt < 4; mt++) {
                uint32_t off = (uint32_t)(mRow[mt] + (((ks * 2 + aKH) ^ mSel[mt]) << 4));
                ldsm4(ah[mt], sb + off);
            }
            #pragma unroll
            for (int ng = 0; ng < 2; ng++) {
                uint32_t off = (uint32_t)(nRow[ng] + (((ks * 2 + bKH) ^ nSel[ng]) << 4));
                ldsm4(bh[ng], sb + 16384 + off);
            }
            #pragma unroll
            for (int mt = 0; mt < 4; mt++)
                #pragma unroll
                for (int nt = 0; nt < 4; nt++)
                    mma16816(acc[mt][nt], ah[mt], &bh[nt >> 1][(nt & 1) * 2]);
        }
        __syncthreads();
    }

    const int mE = lane >> 2;
    const int nE = (lane & 3) << 1;
    #pragma unroll
    for (int mt = 0; mt < 4; mt++) {
        #pragma unroll
        for (int nt = 0; nt < 4; nt++) {
            int m0 = bm + wm * 64 + mt * 16 + mE;
            int n0 = bn + wn * 32 + nt * 8 + nE;
            float b0v = bias[n0], b1v = bias[n0 + 1];
            float v00 = acc[mt][nt][0] + b0v;
            float v01 = acc[mt][nt][1] + b1v;
            float v10 = acc[mt][nt][2] + b0v;
            float v11 = acc[mt][nt][3] + b1v;
            if (mode == 1) {
                v00 = fmaxf(v00, 0.f); v01 = fmaxf(v01, 0.f);
                v10 = fmaxf(v10, 0.f); v11 = fmaxf(v11, 0.f);
            }
            size_t i0 = (size_t)m0 * N + n0;
            size_t i1 = (size_t)(m0 + 8) * N + n0;
            *(__half2*)(outH + i0) = __halves2half2(__float2half(v00), __float2half(v01));
            *(__half2*)(outH + i1) = __halves2half2(__float2half(v10), __float2half(v11));
        }
    }
}

// ---------------- all weights -> fp16 (one launch) ----------------
__global__ void splitAll_kernel(const float* __restrict__ Wqkv,
                                const float* __restrict__ Wo,
                                const float* __restrict__ W1,
                                const float* __restrict__ W2) {
    const int n0 = L_*3*E_*E_;
    const int n1 = n0 + L_*E_*E_;
    const int n2 = n1 + L_*F_*E_;
    const int n3 = n2 + L_*E_*F_;
    int i = blockIdx.x * blockDim.x + threadIdx.x;
    int stride = gridDim.x * blockDim.x;
    for (; i < n3; i += stride) {
        if (i < n0)      wq_h[i]      = __float2half(Wqkv[i]);
        else if (i < n1) wo_h[i - n0] = __float2half(Wo[i - n0]);
        else if (i < n2) w1_h[i - n1] = __float2half(W1[i - n1]);
        else             w2_h[i - n2] = __float2half(W2[i - n2]);
    }
}

// ---------------- warp reductions ----------------
__device__ __forceinline__ float warpSum(float v) {
    #pragma unroll
    for (int o = 16; o > 0; o >>= 1) v += __shfl_xor_sync(0xffffffffu, v, o);
    return v;
}
__device__ __forceinline__ float warpMax(float v) {
    #pragma unroll
    for (int o = 16; o > 0; o >>= 1) v = fmaxf(v, __shfl_xor_sync(0xffffffffu, v, o));
    return v;
}
__device__ float blockSum(float v, float* red) {
    int lane = threadIdx.x & 31, wid = threadIdx.x >> 5;
    v = warpSum(v);
    if (lane == 0) red[wid] = v;
    __syncthreads();
    if (wid == 0) {
        float x = (lane < 8) ? red[lane] : 0.f;
        x = warpSum(x);
        if (lane == 0) red[0] = x;
    }
    __syncthreads();
    float r = red[0];
    __syncthreads();
    return r;
}
__device__ float blockMax(float v, float* red) {
    int lane = threadIdx.x & 31, wid = threadIdx.x >> 5;
    v = warpMax(v);
    if (lane == 0) red[wid] = v;
    __syncthreads();
    if (wid == 0) {
        float x = (lane < 8) ? red[lane] : -1e30f;
        x = warpMax(x);
        if (lane == 0) red[0] = x;
    }
    __syncthreads();
    float r = red[0];
    __syncthreads();
    return r;
}

// ---------------- embed + posenc: 8 rows/block, 1 sincos + rotation ----------------
__global__ __launch_bounds__(256)
void embed_kernel(const float* __restrict__ src,
                  const float* __restrict__ embW,
                  const float* __restrict__ embb) {
    int e = threadIdx.x;
    int m0 = blockIdx.x * 8;
    float w[D_];
    #pragma unroll
    for (int d = 0; d < D_; d++) w[d] = embW[e*D_ + d];
    float be = embb[e];
    const float c = -9.210340371976184f / (float)E_;
    float freq = expf((float)((e >> 1) * 2) * c);
    bool isCos = (e & 1);
    int s0 = m0 & (S_-1);
    float sa, ca, sf, cf;
    sincosf((float)s0 * freq, &sa, &ca);
    sincosf(freq, &sf, &cf);
    #pragma unroll
    for (int r = 0; r < 8; r++) {
        int m = m0 + r;
        const float* sr = src + (size_t)m * D_;
        float acc = 0.f;
        #pragma unroll
        for (int d = 0; d < D_; d++) acc += sr[d] * w[d];
        float pe  = isCos ? ca : sa;
        float val = (acc + be) * 16.0f + pe;
        gx_h[(size_t)m*E_ + e] = __float2half(val);
        float sn = sa*cf + ca*sf;
        ca = ca*cf - sa*sf;
        sa = sn;
    }
}

// ---------------- sparse attention: one block per (head, batch) ----------------
__global__ __launch_bounds__(256)
void attn_kernel(float* __restrict__ out_attn, int l,
                 const float* __restrict__ Wq, const float* __restrict__ bq) {
    int h = blockIdx.x;
    int b = blockIdx.y;
    int t = threadIdx.x;
    __shared__ float xlast[E_];
    __shared__ float qpart[8*HD_];
    __shared__ float q_sh[HD_];
    __shared__ float sc[S_];
    __shared__ float red[32];
    __shared__ float opart[8*HD_];
    __shared__ int lastFlag;
    const float scale = 0.17677669529663687f;
    const __half* kv = gk_h;
    size_t rowLast = (size_t)(b*S_ + (S_-1)) * KV_LD;

    xlast[t] = __half2float(gx_h[(size_t)(b*S_ + (S_-1))*E_ + t]);
    __syncthreads();
    {
        int o = t & 31, cIdx = t >> 5;
        const float* wr = Wq + (size_t)(h*HD_ + o) * E_ + cIdx * 32;
        const float* xr = xlast + cIdx * 32;
        float a = 0.f;
        #pragma unroll
        for (int j = 0; j < 32; j++) a += xr[j] * wr[j];
        qpart[cIdx*HD_ + o] = a;
    }
    __syncthreads();
    if (t < HD_) {
        float a = 0.f;
        #pragma unroll
        for (int cIdx = 0; cIdx < 8; cIdx++) a += qpart[cIdx*HD_ + t];
        q_sh[t] = a + bq[h*HD_ + t];
    }
    __syncthreads();

    // scores: vectorized half2 loads
    float s1, s2;
    {
        const __half2* kr = (const __half2*)(kv + (size_t)(b*S_ + t)*KV_LD + h*HD_);
        float a = 0.f;
        #pragma unroll
        for (int d = 0; d < HD_/2; d++) {
            float2 kf = __half22float2(kr[d]);
            a += q_sh[2*d] * kf.x + q_sh[2*d+1] * kf.y;
        }
        s1 = a * scale;
        int k2 = t + 256;
        if (k2 != S_-1) {
            const __half2* kr2 = (const __half2*)(kv + (size_t)(b*S_ + k2)*KV_LD + h*HD_);
            float a2 = 0.f;
            #pragma unroll
            for (int d = 0; d < HD_/2; d++) {
                float2 kf = __half22float2(kr2[d]);
                a2 += q_sh[2*d] * kf.x + q_sh[2*d+1] * kf.y;
            }
            s2 = a2 * scale;
        } else s2 = -1e30f;
    }
    float mx  = blockMax(fmaxf(s1, s2), red);
    float e1  = expf(s1 - mx);
    float e2  = (t + 256 == S_-1) ? 0.f : expf(s2 - mx);
    float sum = blockSum(e1 + e2, red);
    float inv = 1.0f / sum;
    float a1 = e1*inv, a2 = e2*inv;
    sc[t] = a1; sc[t+256] = a2;
    float* ah = g_ah + ((size_t)b*H_ + h) * S_;
    ah[t]       = a1 * 0.125f;
    ah[t+256]   = a2 * 0.125f;
    __syncthreads();

    // o accumulation: each of 8 groups covers d-pairs via half2
    int g = t >> 5, d = t & 31;
    float oa = 0.f;
    for (int k = g; k < S_-1; k += 8)
        oa += sc[k] * __half2float(kv[(size_t)(b*S_ + k)*KV_LD + E_ + h*HD_ + d]);
    opart[g*HD_ + d] = oa;
    __syncthreads();
    if (t < HD_) {
        float o = 0.f;
        #pragma unroll
        for (int gg = 0; gg < 8; gg++) o += opart[gg*HD_ + t];
        gk_h[rowLast + E_ + h*HD_ + t] = __float2half(o);
    }

    __syncthreads();
    __threadfence();
    if (t == 0) lastFlag = (atomicAdd(&g_tick[b], 1) == H_-1) ? 1 : 0;
    __syncthreads();
    if (lastFlag) {
        if (t == 0) g_tick[b] = 0;
        float s0 = 0.f, ss1 = 0.f;
        #pragma unroll
        for (int hh = 0; hh < H_; hh++) {
            const float* ar = g_ah + ((size_t)b*H_ + hh) * S_;
            s0  += ar[t];
            ss1 += ar[t + 256];
        }
        size_t basei = ((size_t)(l*B_ + b)*S_ + (S_-1)) * S_;
        out_attn[basei + t]       = s0;
        out_attn[basei + t + 256] = ss1;
    }
}

// ---------------- residual + layernorm: warp-per-row, fp16 in/out ----------------
__global__ __launch_bounds__(256)
void ln_kernel(const __half* __restrict__ y, int ldy,
               const float* __restrict__ g, const float* __restrict__ bb) {
    int w = threadIdx.x >> 5, lane = threadIdx.x & 31;
    int m = blockIdx.x * 8 + w;
    size_t xb = (size_t)m * E_ + lane * 4;
    const __half2* x0 = (const __half2*)(gx_h + xb);
    const __half2* x1 = (const __half2*)(gx_h + xb + 128);
    float2 a0 = __half22float2(x0[0]), a1 = __half22float2(x0[1]);
    float2 a2 = __half22float2(x1[0]), a3 = __half22float2(x1[1]);
    const __half2* y0 = (const __half2*)(y + (size_t)m*ldy + lane*4);
    const __half2* y1 = (const __half2*)(y + (size_t)m*ldy + 128 + lane*4);
    float2 f0 = __half22float2(y0[0]), f1 = __half22float2(y0[1]);
    float2 f2 = __half22float2(y1[0]), f3 = __half22float2(y1[1]);
    float v0 = a0.x + f0.x, v1 = a0.y + f0.y, v2 = a1.x + f1.x, v3 = a1.y + f1.y;
    float v4 = a2.x + f2.x, v5 = a2.y + f2.y, v6 = a3.x + f3.x, v7 = a3.y + f3.y;
    float s = v0+v1+v2+v3+v4+v5+v6+v7;
    float mean = warpSum(s) * (1.0f/E_);
    float d0=v0-mean, d1=v1-mean, d2=v2-mean, d3=v3-mean;
    float d4=v4-mean, d5=v5-mean, d6=v6-mean, d7=v7-mean;
    float qs = d0*d0+d1*d1+d2*d2+d3*d3+d4*d4+d5*d5+d6*d6+d7*d7;
    float var = warpSum(qs) * (1.0f/E_);
    float inv = rsqrtf(var + 1e-5f);
    int e0 = lane * 4;
    float4 ga = *(const float4*)(g + e0);
    float4 gc = *(const float4*)(g + e0 + 128);
    float4 ba = *(const float4*)(bb + e0);
    float4 bc = *(const float4*)(bb + e0 + 128);
    float r0 = d0*inv*ga.x + ba.x, r1 = d1*inv*ga.y + ba.y;
    float r2 = d2*inv*ga.z + ba.z, r3 = d3*inv*ga.w + ba.w;
    float r4 = d4*inv*gc.x + bc.x, r5 = d5*inv*gc.y + bc.y;
    float r6 = d6*inv*gc.z + bc.z, r7 = d7*inv*gc.w + bc.w;
    __half2* oh0 = (__half2*)(gx_h + xb);
    __half2* oh1 = (__half2*)(gx_h + xb + 128);
    oh0[0] = __halves2half2(__float2half(r0), __float2half(r1));
    oh0[1] = __halves2half2(__float2half(r2), __float2half(r3));
    oh1[0] = __halves2half2(__float2half(r4), __float2half(r5));
    oh1[1] = __halves2half2(__float2half(r6), __float2half(r7));
}

// ---------------- decode head (2-phase) ----------------
__global__ __launch_bounds__(256)
void final_part1(void) {
    int b = blockIdx.x, c = blockIdx.y, e = threadIdx.x;
    float acc = 0.f;
    int s0 = c * 32;
    #pragma unroll 8
    for (int s = s0; s < s0 + 32; s++)
        acc += fmaxf(__half2float(gx_h[((size_t)b*S_ + s)*E_ + e]), 0.f);
    g_part[((size_t)b*16 + c)*E_ + e] = acc;
}

__global__ __launch_bounds__(256)
void final_part2(const float* __restrict__ decW, float* __restrict__ out) {
    int b = blockIdx.x, e = threadIdx.x;
    __shared__ float xs[E_];
    __shared__ float lg[C_];
    __shared__ float lse_s;
    float acc = 0.f;
    #pragma unroll
    for (int c = 0; c < 16; c++)
        acc += g_part[((size_t)b*16 + c)*E_ + e];
    xs[e] = acc * (1.0f/S_);
    __syncthreads();
    if (e < C_) {
        float a = 0.f;
        for (int i = 0; i < E_; i++) a += xs[i]*decW[e*E_ + i];
        lg[e] = a;
    }
    __syncthreads();
    if (e == 0) {
        float m = -1e30f;
        for (int c = 0; c < C_; c++) m = fmaxf(m, lg[c]);
        float s = 0.f;
        for (int c = 0; c < C_; c++) s += expf(lg[c]-m);
        lse_s = m + logf(s);
    }
    __syncthreads();
    if (e < C_) out[b*C_ + e] = lg[e] - lse_s;
}

// ---------------- attns constant fill (single pass) ----------------
__global__ void fill_attns(float4* __restrict__ p, int n4) {
    int i = blockIdx.x*blockDim.x + threadIdx.x;
    int stride = gridDim.x*blockDim.x;
    for (; i < n4; i += stride) {
        int e0 = i * 4;
        int k0 = e0 & (S_-1);
        int q  = (e0 >> 9) & (S_-1);
        float4 v = make_float4(0.f,0.f,0.f,0.f);
        if (q != S_-1) {
            if (k0 == (q & ~3)) {
                int off = q & 3;
                ((float*)&v)[off] = 1.0f;
            }
        }
        p[i] = v;
    }
}

// ---------------- host ----------------
extern "C" void kernel_launch(void* const* d_in, const int* in_sizes, int n_in,
                              void* d_out, int out_size) {
    const float* src   = (const float*)d_in[0];
    const float* embW  = (const float*)d_in[1];
    const float* embb  = (const float*)d_in[2];
    const float* Wqkv  = (const float*)d_in[3];
    const float* bqkv  = (const float*)d_in[4];
    const float* Wo    = (const float*)d_in[5];
    const float* bo    = (const float*)d_in[6];
    const float* ln1g  = (const float*)d_in[7];
    const float* ln1b  = (const float*)d_in[8];
    const float* ln2g  = (const float*)d_in[9];
    const float* ln2b  = (const float*)d_in[10];
    const float* W1    = (const float*)d_in[11];
    const float* b1    = (const float*)d_in[12];
    const float* W2    = (const float*)d_in[13];
    const float* b2    = (const float*)d_in[14];
    const float* decW  = (const float*)d_in[15];
    float* out = (float*)d_out;
    float* out_attn = out + B_*C_;

    __half *xh, *kh, *hh, *yh;
    __half *wqh, *woh, *w1h, *w2h;
    cudaGetSymbolAddress((void**)&xh, gx_h);
    cudaGetSymbolAddress((void**)&kh, gk_h);
    cudaGetSymbolAddress((void**)&hh, gh_h);
    cudaGetSymbolAddress((void**)&yh, gy_h);
    cudaGetSymbolAddress((void**)&wqh, wq_h);
    cudaGetSymbolAddress((void**)&woh, wo_h);
    cudaGetSymbolAddress((void**)&w1h, w1_h);
    cudaGetSymbolAddress((void**)&w2h, w2_h);

    cudaFuncSetAttribute(gemm_mma, cudaFuncAttributeMaxDynamicSharedMemorySize, SMEM_REQ);

    static cudaStream_t s2 = 0;
    static cudaEvent_t evFork = 0, evSplit = 0, evFill = 0;
    if (!s2) {
        cudaStreamCreateWithFlags(&s2, cudaStreamNonBlocking);
        cudaEventCreateWithFlags(&evFork,  cudaEventDisableTiming);
        cudaEventCreateWithFlags(&evSplit, cudaEventDisableTiming);
        cudaEventCreateWithFlags(&evFill,  cudaEventDisableTiming);
    }

    // fork side stream (one-time): weight split + attns fill
    cudaEventRecord(evFork, 0);
    cudaStreamWaitEvent(s2, evFork, 0);
    splitAll_kernel<<<1536, 256, 0, s2>>>(Wqkv, Wo, W1, W2);
    cudaEventRecord(evSplit, s2);
    int n4 = (L_*B_*S_*S_) / 4;
    fill_attns<<<4096, 256, 0, s2>>>((float4*)out_attn, n4);
    cudaEventRecord(evFill, s2);

    // main stream: embed overlaps side stream
    embed_kernel<<<M_/8, 256>>>(src, embW, embb);
    cudaStreamWaitEvent(0, evSplit, 0);

    for (int l = 0; l < L_; l++) {
        const size_t wq_off = (size_t)l*3*E_*E_;
        // kv = x @ [Wk;Wv]^T + b   [16384,512] -> fp16
        gemm_mma<<<dim3(4, 128), 256, SMEM_REQ>>>(
            xh, E_, wqh + wq_off + (size_t)E_*E_,
            bqkv + l*3*E_ + E_, kh, KV_LD, E_, 0);
        if (l == 0) cudaStreamWaitEvent(0, evFill, 0);
        // attention per (head, batch) + fused ticket combine
        attn_kernel<<<dim3(H_, B_), 256>>>(out_attn, l, Wqkv + wq_off, bqkv + l*3*E_);
        // y = o @ Wo^T + bo  (o = v-view of kh, lda=512) -> fp16
        gemm_mma<<<dim3(2, 128), 256, SMEM_REQ>>>(
            kh + E_, KV_LD, woh + (size_t)l*E_*E_,
            bo + l*E_, yh, E_, E_, 0);
        // x = LN1(x + y)
        ln_kernel<<<M_/8, 256>>>(yh, E_, ln1g + l*E_, ln1b + l*E_);
        // h = relu(x @ W1^T + b1) -> fp16
        gemm_mma<<<dim3(8, 128), 256, SMEM_REQ>>>(
            xh, E_, w1h + (size_t)l*F_*E_,
            b1 + l*F_, hh, F_, E_, 1);
        // y = h @ W2^T + b2 -> fp16
        gemm_mma<<<dim3(2, 128), 256, SMEM_REQ>>>(
            hh, F_, w2h + (size_t)l*E_*F_,
            b2 + l*E_, yh, E_, F_, 0);
        // x = LN2(x + y)
        ln_kernel<<<M_/8, 256>>>(yh, E_, ln2g + l*E_, ln2b + l*E_);
    }

    final_part1<<<dim3(B_, 16), 256>>>();
    final_part2<<<B_, 256>>>(decW, out);
}

// round 16
// speedup vs baseline: 1.0916x; 1.0012x over previous
#include <cuda_runtime.h>
#include <cuda_fp16.h>
#include <math.h>
#include <stdint.h>

#define B_  32
#define S_  512
#define D_  9
#define E_  256
#define F_  1024
#define L_  4
#define C_  10
#define H_  8
#define HD_ 32
#define M_  (B_*S_)          // 16384 rows
#define KV_LD 512

// ---------------- scratch (static __device__, no allocs) ----------------
__device__ float g_ah[B_*H_*S_];      // per-head attn last rows (scaled 1/8)
__device__ float g_part[B_*16*E_];    // decode partial sums
__device__ int   g_tick[B_];          // combine tickets (self-resetting)

__device__ __half gx_h[M_*E_];        // activations fp16 (residual master)
__device__ __half gk_h[M_*KV_LD];     // k(0..255), v->o(256..511) fp16
__device__ __half gh_h[M_*F_];        // ffn hidden fp16
__device__ __half gy_h[M_*E_];        // proj/ffn2 out fp16
__device__ __half wq_h[L_*3*E_*E_];
__device__ __half wo_h[L_*E_*E_];
__device__ __half w1_h[L_*F_*E_];
__device__ __half w2_h[L_*E_*F_];

// ================= PTX helpers (target-portable) =================
__device__ __forceinline__ uint32_t smem_u32(const void* p) {
    uint32_t a;
    asm("{ .reg .u64 t; cvta.to.shared.u64 t, %1; cvt.u32.u64 %0, t; }" : "=r"(a) : "l"(p));
    return a;
}
__device__ __forceinline__ void cp16(uint32_t dst, const void* src) {
    asm volatile("cp.async.cg.shared.global [%0], [%1], 16;\n" :: "r"(dst), "l"(src));
}
__device__ __forceinline__ void ldsm4(uint32_t* r, uint32_t addr) {
    asm volatile("ldmatrix.sync.aligned.m8n8.x4.shared.b16 {%0,%1,%2,%3}, [%4];"
        : "=r"(r[0]), "=r"(r[1]), "=r"(r[2]), "=r"(r[3]) : "r"(addr));
}
__device__ __forceinline__ void mma16816(float* d, const uint32_t* a, const uint32_t* b) {
    asm volatile("mma.sync.aligned.m16n8k16.row.col.f32.f16.f16.f32 "
        "{%0,%1,%2,%3}, {%4,%5,%6,%7}, {%8,%9}, {%0,%1,%2,%3};"
        : "+f"(d[0]), "+f"(d[1]), "+f"(d[2]), "+f"(d[3])
        : "r"(a[0]), "r"(a[1]), "r"(a[2]), "r"(a[3]), "r"(b[0]), "r"(b[1]));
}

// ================= GEMM: C[M,N] = A[M,K] @ B[N,K]^T + bias =================
// BM=BN=128, BK=64, 256 threads, warp grid 2x4, warp tile 64x32,
// 2-stage cp.async pipeline, 2 CTAs/SM. (PROVEN optimum — frozen.)
#define STAGES 2
#define STAGE_BYTES 32768          // A 16K | B 16K
#define SMEM_REQ (STAGES*STAGE_BYTES + 1024)

__global__ __launch_bounds__(256, 2)
void gemm_mma(const __half* __restrict__ Ah, int lda,
              const __half* __restrict__ Bh,
              const float* __restrict__ bias,
              __half* __restrict__ outH,
              int N, int K, int mode)
{
    extern __shared__ char dsm[];
    const uint32_t base = (smem_u32(dsm) + 1023u) & ~1023u;
    const int tid = threadIdx.x;
    const int lane = tid & 31, wid = tid >> 5;
    const int bm = blockIdx.y * 128, bn = blockIdx.x * 128;
    const int wm = wid >> 2, wn = wid & 3;

    const size_t lda2 = (size_t)lda * 2, ldb2 = (size_t)K * 2;
    const char* gAh = (const char*)Ah + (size_t)bm * lda2;
    const char* gBh = (const char*)Bh + (size_t)bn * ldb2;

    const int cc  = tid & 7;
    const int rr0 = tid >> 3;

    auto load_stage = [&](int kt, int s) {
        uint32_t st = base + (uint32_t)s * STAGE_BYTES;
        size_t gk = (size_t)kt * 128 + (size_t)cc * 16;
        #pragma unroll
        for (int j = 0; j < 4; j++) {
            int r = rr0 + j * 32;
            uint32_t d = (uint32_t)(r * 128 + ((cc ^ (r & 7)) << 4));
            cp16(st + d,           gAh + (size_t)r * lda2 + gk);
            cp16(st + 16384 + d,   gBh + (size_t)r * ldb2 + gk);
        }
        asm volatile("cp.async.commit_group;\n" ::: "memory");
    };

    const int q = lane >> 3, r8 = lane & 7;
    int mRow[4], mSel[4];
    #pragma unroll
    for (int mt = 0; mt < 4; mt++) {
        int m = wm * 64 + mt * 16 + r8 + (q & 1) * 8;
        mRow[mt] = m * 128; mSel[mt] = m & 7;
    }
    const int aKH = q >> 1;
    int nRow[2], nSel[2];
    #pragma unroll
    for (int ng = 0; ng < 2; ng++) {
        int n = wn * 32 + ng * 16 + r8 + (q >> 1) * 8;
        nRow[ng] = n * 128; nSel[ng] = n & 7;
    }
    const int bKH = q & 1;

    float acc[4][4][4];
    #pragma unroll
    for (int a = 0; a < 4; a++)
        #pragma unroll
        for (int b = 0; b < 4; b++)
            #pragma unroll
            for (int c = 0; c < 4; c++) acc[a][b][c] = 0.f;

    const int nkt = K >> 6;
    load_stage(0, 0);

    for (int kt = 0; kt < nkt; kt++) {
        if (kt + 1 < nkt) load_stage(kt + 1, (kt + 1) & 1);
        else asm volatile("cp.async.commit_group;\n" ::: "memory");
        asm volatile("cp.async.wait_group 1;\n" ::: "memory");
        __syncthreads();

        const uint32_t sb = base + (uint32_t)(kt & 1) * STAGE_BYTES;
        #pragma unroll
        for (int ks = 0; ks < 4; ks++) {
            uint32_t ah[4][4], bh[2][4];
            #pragma unroll
            for (int mt = 0; mt < 4; mt++) {
                uint32_t off = (uint32_t)(mRow[mt] + (((ks * 2 + aKH) ^ mSel[mt]) << 4));
                ldsm4(ah[mt], sb + off);
            }
            #pragma unroll
            for (int ng = 0; ng < 2; ng++) {
                uint32_t off = (uint32_t)(nRow[ng] + (((ks * 2 + bKH) ^ nSel[ng]) << 4));
                ldsm4(bh[ng], sb + 16384 + off);
            }
            #pragma unroll
            for (int mt = 0; mt < 4; mt++)
                #pragma unroll
                for (int nt = 0; nt < 4; nt++)
                    mma16816(acc[mt][nt], ah[mt], &bh[nt >> 1][(nt & 1) * 2]);
        }
        __syncthreads();
    }

    const int mE = lane >> 2;
    const int nE = (lane & 3) << 1;
    #pragma unroll
    for (int mt = 0; mt < 4; mt++) {
        #pragma unroll
        for (int nt = 0; nt < 4; nt++) {
            int m0 = bm + wm * 64 + mt * 16 + mE;
            int n0 = bn + wn * 32 + nt * 8 + nE;
            float b0v = bias[n0], b1v = bias[n0 + 1];
            float v00 = acc[mt][nt][0] + b0v;
            float v01 = acc[mt][nt][1] + b1v;
            float v10 = acc[mt][nt][2] + b0v;
            float v11 = acc[mt][nt][3] + b1v;
            if (mode == 1) {
                v00 = fmaxf(v00, 0.f); v01 = fmaxf(v01, 0.f);
                v10 = fmaxf(v10, 0.f); v11 = fmaxf(v11, 0.f);
            }
            size_t i0 = (size_t)m0 * N + n0;
            size_t i1 = (size_t)(m0 + 8) * N + n0;
            *(__half2*)(outH + i0) = __halves2half2(__float2half(v00), __float2half(v01));
            *(__half2*)(outH + i1) = __halves2half2(__float2half(v10), __float2half(v11));
        }
    }
}

// ---------------- all weights -> fp16 (one launch, float2->half2) ----------------
__global__ void splitAll_kernel(const float* __restrict__ Wqkv,
                                const float* __restrict__ Wo,
                                const float* __restrict__ W1,
                                const float* __restrict__ W2) {
    const int n0 = L_*3*E_*E_;
    const int n1 = n0 + L_*E_*E_;
    const int n2 = n1 + L_*F_*E_;
    const int n3 = n2 + L_*E_*F_;
    int i2 = blockIdx.x * blockDim.x + threadIdx.x;
    int stride = gridDim.x * blockDim.x;
    for (; i2 < n3/2; i2 += stride) {
        int i = i2 * 2;
        float2 v; __half2* dst;
        if (i < n0)      { v = *(const float2*)(Wqkv + i);       dst = (__half2*)(wq_h + i); }
        else if (i < n1) { v = *(const float2*)(Wo + (i - n0));  dst = (__half2*)(wo_h + (i - n0)); }
        else if (i < n2) { v = *(const float2*)(W1 + (i - n1));  dst = (__half2*)(w1_h + (i - n1)); }
        else             { v = *(const float2*)(W2 + (i - n2));  dst = (__half2*)(w2_h + (i - n2)); }
        *dst = __halves2half2(__float2half(v.x), __float2half(v.y));
    }
}

// ---------------- warp reductions ----------------
__device__ __forceinline__ float warpSum(float v) {
    #pragma unroll
    for (int o = 16; o > 0; o >>= 1) v += __shfl_xor_sync(0xffffffffu, v, o);
    return v;
}
__device__ __forceinline__ float warpMax(float v) {
    #pragma unroll
    for (int o = 16; o > 0; o >>= 1) v = fmaxf(v, __shfl_xor_sync(0xffffffffu, v, o));
    return v;
}
__device__ float blockSum(float v, float* red) {
    int lane = threadIdx.x & 31, wid = threadIdx.x >> 5;
    v = warpSum(v);
    if (lane == 0) red[wid] = v;
    __syncthreads();
    if (wid == 0) {
        float x = (lane < 8) ? red[lane] : 0.f;
        x = warpSum(x);
        if (lane == 0) red[0] = x;
    }
    __syncthreads();
    float r = red[0];
    __syncthreads();
    return r;
}
__device__ float blockMax(float v, float* red) {
    int lane = threadIdx.x & 31, wid = threadIdx.x >> 5;
    v = warpMax(v);
    if (lane == 0) red[wid] = v;
    __syncthreads();
    if (wid == 0) {
        float x = (lane < 8) ? red[lane] : -1e30f;
        x = warpMax(x);
        if (lane == 0) red[0] = x;
    }
    __syncthreads();
    float r = red[0];
    __syncthreads();
    return r;
}

// ---------------- embed + posenc: 8 rows/block, 1 sincos + rotation ----------------
__global__ __launch_bounds__(256)
void embed_kernel(const float* __restrict__ src,
                  const float* __restrict__ embW,
                  const float* __restrict__ embb) {
    int e = threadIdx.x;
    int m0 = blockIdx.x * 8;
    float w[D_];
    #pragma unroll
    for (int d = 0; d < D_; d++) w[d] = embW[e*D_ + d];
    float be = embb[e];
    const float c = -9.210340371976184f / (float)E_;
    float freq = expf((float)((e >> 1) * 2) * c);
    bool isCos = (e & 1);
    int s0 = m0 & (S_-1);
    float sa, ca, sf, cf;
    sincosf((float)s0 * freq, &sa, &ca);
    sincosf(freq, &sf, &cf);
    #pragma unroll
    for (int r = 0; r < 8; r++) {
        int m = m0 + r;
        const float* sr = src + (size_t)m * D_;
        float acc = 0.f;
        #pragma unroll
        for (int d = 0; d < D_; d++) acc += sr[d] * w[d];
        float pe  = isCos ? ca : sa;
        float val = (acc + be) * 16.0f + pe;
        gx_h[(size_t)m*E_ + e] = __float2half(val);
        float sn = sa*cf + ca*sf;
        ca = ca*cf - sa*sf;
        sa = sn;
    }
}

// ---------------- sparse attention: one block per (head, batch) ----------------
__global__ __launch_bounds__(256)
void attn_kernel(float* __restrict__ out_attn, int l,
                 const float* __restrict__ Wq, const float* __restrict__ bq) {
    int h = blockIdx.x;
    int b = blockIdx.y;
    int t = threadIdx.x;
    __shared__ float xlast[E_];
    __shared__ float qpart[8*HD_];
    __shared__ float q_sh[HD_];
    __shared__ float sc[S_];
    __shared__ float red[32];
    __shared__ float opart[16*HD_];
    __shared__ int lastFlag;
    const float scale = 0.17677669529663687f;
    const __half* kv = gk_h;
    size_t rowLast = (size_t)(b*S_ + (S_-1)) * KV_LD;

    xlast[t] = __half2float(gx_h[(size_t)(b*S_ + (S_-1))*E_ + t]);
    __syncthreads();
    {
        int o = t & 31, cIdx = t >> 5;
        const float* wr = Wq + (size_t)(h*HD_ + o) * E_ + cIdx * 32;
        const float* xr = xlast + cIdx * 32;
        float a = 0.f;
        #pragma unroll
        for (int j = 0; j < 32; j++) a += xr[j] * wr[j];
        qpart[cIdx*HD_ + o] = a;
    }
    __syncthreads();
    if (t < HD_) {
        float a = 0.f;
        #pragma unroll
        for (int cIdx = 0; cIdx < 8; cIdx++) a += qpart[cIdx*HD_ + t];
        q_sh[t] = a + bq[h*HD_ + t];
    }
    __syncthreads();

    // scores: vectorized half2 loads
    float s1, s2;
    {
        const __half2* kr = (const __half2*)(kv + (size_t)(b*S_ + t)*KV_LD + h*HD_);
        float a = 0.f;
        #pragma unroll
        for (int d = 0; d < HD_/2; d++) {
            float2 kf = __half22float2(kr[d]);
            a += q_sh[2*d] * kf.x + q_sh[2*d+1] * kf.y;
        }
        s1 = a * scale;
        int k2 = t + 256;
        if (k2 != S_-1) {
            const __half2* kr2 = (const __half2*)(kv + (size_t)(b*S_ + k2)*KV_LD + h*HD_);
            float a2 = 0.f;
            #pragma unroll
            for (int d = 0; d < HD_/2; d++) {
                float2 kf = __half22float2(kr2[d]);
                a2 += q_sh[2*d] * kf.x + q_sh[2*d+1] * kf.y;
            }
            s2 = a2 * scale;
        } else s2 = -1e30f;
    }
    float mx  = blockMax(fmaxf(s1, s2), red);
    float e1  = expf(s1 - mx);
    float e2  = (t + 256 == S_-1) ? 0.f : expf(s2 - mx);
    float sum = blockSum(e1 + e2, red);
    float inv = 1.0f / sum;
    float a1 = e1*inv, a2 = e2*inv;
    sc[t] = a1; sc[t+256] = a2;
    float* ah = g_ah + ((size_t)b*H_ + h) * S_;
    ah[t]       = a1 * 0.125f;
    ah[t+256]   = a2 * 0.125f;
    __syncthreads();

    // o accumulation: 16 groups x 16 half2 dim-pairs
    {
        int g = t >> 4;            // 0..15
        int dp = t & 15;           // dim pair -> dims 2dp, 2dp+1
        float ox = 0.f, oy = 0.f;
        const __half2* vb = (const __half2*)(kv + E_ + h*HD_) + dp;
        for (int k = g; k < S_-1; k += 16) {
            float2 vf = __half22float2(vb[(size_t)(b*S_ + k)*(KV_LD/2)]);
            float a = sc[k];
            ox += a * vf.x; oy += a * vf.y;
        }
        opart[g*HD_ + 2*dp]     = ox;
        opart[g*HD_ + 2*dp + 1] = oy;
    }
    __syncthreads();
    if (t < HD_) {
        float o = 0.f;
        #pragma unroll
        for (int gg = 0; gg < 16; gg++) o += opart[gg*HD_ + t];
        gk_h[rowLast + E_ + h*HD_ + t] = __float2half(o);
    }

    __syncthreads();
    __threadfence();
    if (t == 0) lastFlag = (atomicAdd(&g_tick[b], 1) == H_-1) ? 1 : 0;
    __syncthreads();
    if (lastFlag) {
        if (t == 0) g_tick[b] = 0;
        float s0 = 0.f, ss1 = 0.f;
        #pragma unroll
        for (int hh = 0; hh < H_; hh++) {
            const float* ar = g_ah + ((size_t)b*H_ + hh) * S_;
            s0  += ar[t];
            ss1 += ar[t + 256];
        }
        size_t basei = ((size_t)(l*B_ + b)*S_ + (S_-1)) * S_;
        out_attn[basei + t]       = s0;
        out_attn[basei + t + 256] = ss1;
    }
}

// ---------------- residual + layernorm: warp-per-row, fp16 in/out ----------------
__global__ __launch_bounds__(256)
void ln_kernel(const __half* __restrict__ y, int ldy,
               const float* __restrict__ g, const float* __restrict__ bb) {
    int w = threadIdx.x >> 5, lane = threadIdx.x & 31;
    int m = blockIdx.x * 8 + w;
    size_t xb = (size_t)m * E_ + lane * 4;
    const __half2* x0 = (const __half2*)(gx_h + xb);
    const __half2* x1 = (const __half2*)(gx_h + xb + 128);
    float2 a0 = __half22float2(x0[0]), a1 = __half22float2(x0[1]);
    float2 a2 = __half22float2(x1[0]), a3 = __half22float2(x1[1]);
    const __half2* y0 = (const __half2*)(y + (size_t)m*ldy + lane*4);
    const __half2* y1 = (const __half2*)(y + (size_t)m*ldy + 128 + lane*4);
    float2 f0 = __half22float2(y0[0]), f1 = __half22float2(y0[1]);
    float2 f2 = __half22float2(y1[0]), f3 = __half22float2(y1[1]);
    float v0 = a0.x + f0.x, v1 = a0.y + f0.y, v2 = a1.x + f1.x, v3 = a1.y + f1.y;
    float v4 = a2.x + f2.x, v5 = a2.y + f2.y, v6 = a3.x + f3.x, v7 = a3.y + f3.y;
    float s = v0+v1+v2+v3+v4+v5+v6+v7;
    float mean = warpSum(s) * (1.0f/E_);
    float d0=v0-mean, d1=v1-mean, d2=v2-mean, d3=v3-mean;
    float d4=v4-mean, d5=v5-mean, d6=v6-mean, d7=v7-mean;
    float qs = d0*d0+d1*d1+d2*d2+d3*d3+d4*d4+d5*d5+d6*d6+d7*d7;
    float var = warpSum(qs) * (1.0f/E_);
    float inv = rsqrtf(var + 1e-5f);
    int e0 = lane * 4;
    float4 ga = *(const float4*)(g + e0);
    float4 gc = *(const float4*)(g + e0 + 128);
    float4 ba = *(const float4*)(bb + e0);
    float4 bc = *(const float4*)(bb + e0 + 128);
    float r0 = d0*inv*ga.x + ba.x, r1 = d1*inv*ga.y + ba.y;
    float r2 = d2*inv*ga.z + ba.z, r3 = d3*inv*ga.w + ba.w;
    float r4 = d4*inv*gc.x + bc.x, r5 = d5*inv*gc.y + bc.y;
    float r6 = d6*inv*gc.z + bc.z, r7 = d7*inv*gc.w + bc.w;
    __half2* oh0 = (__half2*)(gx_h + xb);
    __half2* oh1 = (__half2*)(gx_h + xb + 128);
    oh0[0] = __halves2half2(__float2half(r0), __float2half(r1));
    oh0[1] = __halves2half2(__float2half(r2), __float2half(r3));
    oh1[0] = __halves2half2(__float2half(r4), __float2half(r5));
    oh1[1] = __halves2half2(__float2half(r6), __float2half(r7));
}

// ---------------- decode head (2-phase) ----------------
__global__ __launch_bounds__(128)
void final_part1(void) {
    int b = blockIdx.x, c = blockIdx.y, p = threadIdx.x;   // p = dim pair
    float ax = 0.f, ay = 0.f;
    int s0 = c * 32;
    const __half2* xp = (const __half2*)gx_h + p;
    #pragma unroll 8
    for (int s = s0; s < s0 + 32; s++) {
        float2 v = __half22float2(xp[(size_t)(b*S_ + s)*(E_/2)]);
        ax += fmaxf(v.x, 0.f);
        ay += fmaxf(v.y, 0.f);
    }
    g_part[((size_t)b*16 + c)*E_ + 2*p]     = ax;
    g_part[((size_t)b*16 + c)*E_ + 2*p + 1] = ay;
}

__global__ __launch_bounds__(256)
void final_part2(const float* __restrict__ decW, float* __restrict__ out) {
    int b = blockIdx.x, e = threadIdx.x;
    __shared__ float xs[E_];
    __shared__ float lg[C_];
    __shared__ float lse_s;
    float acc = 0.f;
    #pragma unroll
    for (int c = 0; c < 16; c++)
        acc += g_part[((size_t)b*16 + c)*E_ + e];
    xs[e] = acc * (1.0f/S_);
    __syncthreads();
    if (e < C_) {
        float a = 0.f;
        for (int i = 0; i < E_; i++) a += xs[i]*decW[e*E_ + i];
        lg[e] = a;
    }
    __syncthreads();
    if (e == 0) {
        float m = -1e30f;
        for (int c = 0; c < C_; c++) m = fmaxf(m, lg[c]);
        float s = 0.f;
        for (int c = 0; c < C_; c++) s += expf(lg[c]-m);
        lse_s = m + logf(s);
    }
    __syncthreads();
    if (e < C_) out[b*C_ + e] = lg[e] - lse_s;
}

// ---------------- attns constant fill (single pass) ----------------
__global__ void fill_attns(float4* __restrict__ p, int n4) {
    int i = blockIdx.x*blockDim.x + threadIdx.x;
    int stride = gridDim.x*blockDim.x;
    for (; i < n4; i += stride) {
        int e0 = i * 4;
        int k0 = e0 & (S_-1);
        int q  = (e0 >> 9) & (S_-1);
        float4 v = make_float4(0.f,0.f,0.f,0.f);
        if (q != S_-1) {
            if (k0 == (q & ~3)) {
                int off = q & 3;
                ((float*)&v)[off] = 1.0f;
            }
        }
        p[i] = v;
    }
}

// ---------------- host ----------------
extern "C" void kernel_launch(void* const* d_in, const int* in_sizes, int n_in,
                              void* d_out, int out_size) {
    const float* src   = (const float*)d_in[0];
    const float* embW  = (const float*)d_in[1];
    const float* embb  = (const float*)d_in[2];
    const float* Wqkv  = (const float*)d_in[3];
    const float* bqkv  = (const float*)d_in[4];
    const float* Wo    = (const float*)d_in[5];
    const float* bo    = (const float*)d_in[6];
    const float* ln1g  = (const float*)d_in[7];
    const float* ln1b  = (const float*)d_in[8];
    const float* ln2g  = (const float*)d_in[9];
    const float* ln2b  = (const float*)d_in[10];
    const float* W1    = (const float*)d_in[11];
    const float* b1    = (const float*)d_in[12];
    const float* W2    = (const float*)d_in[13];
    const float* b2    = (const float*)d_in[14];
    const float* decW  = (const float*)d_in[15];
    float* out = (float*)d_out;
    float* out_attn = out + B_*C_;

    __half *xh, *kh, *hh, *yh;
    __half *wqh, *woh, *w1h, *w2h;
    cudaGetSymbolAddress((void**)&xh, gx_h);
    cudaGetSymbolAddress((void**)&kh, gk_h);
    cudaGetSymbolAddress((void**)&hh, gh_h);
    cudaGetSymbolAddress((void**)&yh, gy_h);
    cudaGetSymbolAddress((void**)&wqh, wq_h);
    cudaGetSymbolAddress((void**)&woh, wo_h);
    cudaGetSymbolAddress((void**)&w1h, w1_h);
    cudaGetSymbolAddress((void**)&w2h, w2_h);

    cudaFuncSetAttribute(gemm_mma, cudaFuncAttributeMaxDynamicSharedMemorySize, SMEM_REQ);

    static cudaStream_t s2 = 0;
    static cudaEvent_t evFork = 0, evSplit = 0, evFill = 0;
    if (!s2) {
        cudaStreamCreateWithFlags(&s2, cudaStreamNonBlocking);
        cudaEventCreateWithFlags(&evFork,  cudaEventDisableTiming);
        cudaEventCreateWithFlags(&evSplit, cudaEventDisableTiming);
        cudaEventCreateWithFlags(&evFill,  cudaEventDisableTiming);
    }

    // fork side stream (one-time): weight split + attns fill
    cudaEventRecord(evFork, 0);
    cudaStreamWaitEvent(s2, evFork, 0);
    splitAll_kernel<<<1536, 256, 0, s2>>>(Wqkv, Wo, W1, W2);
    cudaEventRecord(evSplit, s2);
    int n4 = (L_*B_*S_*S_) / 4;
    fill_attns<<<4096, 256, 0, s2>>>((float4*)out_attn, n4);
    cudaEventRecord(evFill, s2);

    // main stream: embed overlaps side stream
    embed_kernel<<<M_/8, 256>>>(src, embW, embb);
    cudaStreamWaitEvent(0, evSplit, 0);

    for (int l = 0; l < L_; l++) {
        const size_t wq_off = (size_t)l*3*E_*E_;
        // kv = x @ [Wk;Wv]^T + b   [16384,512] -> fp16
        gemm_mma<<<dim3(4, 128), 256, SMEM_REQ>>>(
            xh, E_, wqh + wq_off + (size_t)E_*E_,
            bqkv + l*3*E_ + E_, kh, KV_LD, E_, 0);
        if (l == 0) cudaStreamWaitEvent(0, evFill, 0);
        // attention per (head, batch) + fused ticket combine
        attn_kernel<<<dim3(H_, B_), 256>>>(out_attn, l, Wqkv + wq_off, bqkv + l*3*E_);
        // y = o @ Wo^T + bo  (o = v-view of kh, lda=512) -> fp16
        gemm_mma<<<dim3(2, 128), 256, SMEM_REQ>>>(
            kh + E_, KV_LD, woh + (size_t)l*E_*E_,
            bo + l*E_, yh, E_, E_, 0);
        // x = LN1(x + y)
        ln_kernel<<<M_/8, 256>>>(yh, E_, ln1g + l*E_, ln1b + l*E_);
        // h = relu(x @ W1^T + b1) -> fp16
        gemm_mma<<<dim3(8, 128), 256, SMEM_REQ>>>(
            xh, E_, w1h + (size_t)l*F_*E_,
            b1 + l*F_, hh, F_, E_, 1);
        // y = h @ W2^T + b2 -> fp16
        gemm_mma<<<dim3(2, 128), 256, SMEM_REQ>>>(
            hh, F_, w2h + (size_t)l*E_*F_,
            b2 + l*E_, yh, E_, F_, 0);
        // x = LN2(x + y)
        ln_kernel<<<M_/8, 256>>>(yh, E_, ln2g + l*E_, ln2b + l*E_);
    }

    final_part1<<<dim3(B_, 16), 128>>>();
    final_part2<<<B_, 256>>>(decW, out);
}